// round 3
// baseline (speedup 1.0000x reference)
#include <cuda_runtime.h>
#include <cstdint>

// Haar IDWT (reference's LH-uses-LPF-twice quirk folded into LL by linearity):
//   out[n,a,b] = 0.5 * ((ll+lh) + sb*hl + sa*sb*hh)
//   sa = (a even ? -1 : +1), sb likewise; (ll,lh,hl,hh) = in[n, a>>1, b>>1, :]
//
// One thread = 4 consecutive input pixels -> 8x2 output block.
//   loads : 4x float4, front-batched (MLP_p1=4), 2KB contiguous per warp
//   stores: 2x float4 per output row x 2 rows, coalesced
// R3: identical mapping to R2 but with DEFAULT cache policy (no .cs) —
// the evict-first hints were the R2 regression suspect.

namespace {
constexpr int B = 16;
constexpr int H = 512;
constexpr int W = 512;
constexpr int QUADS_PER_ROW = W / 4;                 // 128
constexpr int TOTAL = B * H * QUADS_PER_ROW;         // 1,048,576 threads
constexpr int OW4 = (2 * W) / 4;                     // 256 float4 per output row
}

__global__ void __launch_bounds__(256) idwt_haar_kernel(
    const float4* __restrict__ in, float4* __restrict__ out)
{
    int idx = blockIdx.x * blockDim.x + threadIdx.x;

    int q = idx & (QUADS_PER_ROW - 1);       // quad index 0..127
    int r = (idx >> 7) & (H - 1);            // input row 0..511
    int n = idx >> 16;                       // batch 0..15

    const float4* p = in + ((size_t)n * H + r) * W + 4 * q;
    float4 p0 = p[0];
    float4 p1 = p[1];
    float4 p2 = p[2];
    float4 p3 = p[3];

    float e0 = 0.5f * (p0.x + p0.y), hl0 = 0.5f * p0.z, hh0 = 0.5f * p0.w;
    float e1 = 0.5f * (p1.x + p1.y), hl1 = 0.5f * p1.z, hh1 = 0.5f * p1.w;
    float e2 = 0.5f * (p2.x + p2.y), hl2 = 0.5f * p2.z, hh2 = 0.5f * p2.w;
    float e3 = 0.5f * (p3.x + p3.y), hl3 = 0.5f * p3.z, hh3 = 0.5f * p3.w;

    // top row: a = 2r (even, sa=-1); even col sb=-1, odd col sb=+1
    float4 t0, t1, b0, b1;
    t0.x = e0 - hl0 + hh0;  t0.y = e0 + hl0 - hh0;
    t0.z = e1 - hl1 + hh1;  t0.w = e1 + hl1 - hh1;
    t1.x = e2 - hl2 + hh2;  t1.y = e2 + hl2 - hh2;
    t1.z = e3 - hl3 + hh3;  t1.w = e3 + hl3 - hh3;
    // bottom row: a = 2r+1 (odd, sa=+1)
    b0.x = e0 - hl0 - hh0;  b0.y = e0 + hl0 + hh0;
    b0.z = e1 - hl1 - hh1;  b0.w = e1 + hl1 + hh1;
    b1.x = e2 - hl2 - hh2;  b1.y = e2 + hl2 + hh2;
    b1.z = e3 - hl3 - hh3;  b1.w = e3 + hl3 + hh3;

    // output float4 index: row (2r) of image n, starting col 8q
    size_t o = ((size_t)n * 1024 + 2 * r) * OW4 + 2 * q;
    out[o]           = t0;
    out[o + 1]       = t1;
    out[o + OW4]     = b0;
    out[o + OW4 + 1] = b1;
}

extern "C" void kernel_launch(void* const* d_in, const int* in_sizes, int n_in,
                              void* d_out, int out_size)
{
    const float4* in = (const float4*)d_in[0];
    float4* out = (float4*)d_out;
    idwt_haar_kernel<<<TOTAL / 256, 256>>>(in, out);
}

// round 4
// speedup vs baseline: 1.2159x; 1.2159x over previous
#include <cuda_runtime.h>
#include <cstdint>

// Haar IDWT (reference's LH-uses-LPF-twice quirk folded into LL by linearity):
//   out[n,a,b] = 0.5 * ((ll+lh) + sb*hl + sa*sb*hh)
//   sa = (a even ? -1 : +1), sb likewise; (ll,lh,hl,hh) = in[n, a>>1, b>>1, :]
//
// R4 mapping: warp-strided, every memory instruction lane-contiguous dense.
//   Warp w owns input pixels [128w, 128w+128). Lane t loads pixels
//   128w+t, +32, +64, +96 -> each LDG.128 is a dense 512B (4 full lines).
//   Each pixel -> one float2 per output row; each STG.64 is a dense 256B.
//   MLP_p1 = 4, zero cross-lane comm, no smem.

namespace {
constexpr int B = 16;
constexpr int H = 512;
constexpr int W = 512;
constexpr int TOTAL = B * H * W / 4;   // 1,048,576 threads (4 pixels each)
}

__global__ void __launch_bounds__(256) idwt_haar_kernel(
    const float4* __restrict__ in, float2* __restrict__ out)
{
    int tid  = blockIdx.x * 256 + threadIdx.x;
    int lane = threadIdx.x & 31;
    int warp = tid >> 5;
    int base = (warp << 7) + lane;          // pixel index for k=0

    // front-batched dense loads (MLP_p1 = 4)
    float4 p0 = in[base];
    float4 p1 = in[base + 32];
    float4 p2 = in[base + 64];
    float4 p3 = in[base + 96];

    // all 4 pixels share (n, r): 128-pixel warp segments never straddle a row
    int n    = base >> 18;                  // 512*512 = 2^18 pixels/image
    int r    = (base >> 9) & (H - 1);       // input row
    int col0 = base & (W - 1);              // input col of k=0

    // float2 index of output row 2r, col 2*col0: (n*1024 + 2r)*512 + col0
    size_t otop = ((((size_t)n << 10) + 2 * r) << 9) + col0;
    size_t obot = otop + 512;               // next output row

    float4 p[4] = {p0, p1, p2, p3};
#pragma unroll
    for (int k = 0; k < 4; k++) {
        float e  = 0.5f * (p[k].x + p[k].y);
        float hl = 0.5f * p[k].z;
        float hh = 0.5f * p[k].w;
        // top row a=2r even (sa=-1): [e - hl + hh, e + hl - hh]
        // bot row a=2r+1 odd (sa=+1): [e - hl - hh, e + hl + hh]
        out[otop + 32 * k] = make_float2(e - hl + hh, e + hl - hh);
        out[obot + 32 * k] = make_float2(e - hl - hh, e + hl + hh);
    }
}

extern "C" void kernel_launch(void* const* d_in, const int* in_sizes, int n_in,
                              void* d_out, int out_size)
{
    const float4* in = (const float4*)d_in[0];
    float2* out = (float2*)d_out;
    idwt_haar_kernel<<<TOTAL / 256, 256>>>(in, out);
}